// round 1
// baseline (speedup 1.0000x reference)
#include <cuda_runtime.h>

// Spikformer SSA: T=4, B=8, C=512, N=1024, H=8, d=64
// Pipeline:
//   K1 gemm1 (fp32): Y[p,b,c,n] = W_p @ x_p + bias   (T-invariant -> computed once)
//   K2 branch BN stats (fp64 accum)
//   K3 spike+pack: LIF(4 steps, const input) -> bitmasks
//        q packed over d (u64 per (t,b,h,n)); k,v packed over n (16 u64 per (t,b,h,d))
//   K4 ktv[t,b,h,d,e] = popcount over n  (exact integers)
//   K5 att = q-select-sum of ktv rows, *0.125, attn-LIF(0.5) -> binary X (exact)
//   K6 gemm3 (fp32): Z = proj_w @ X + b
//   K7 final BN stats
//   K8 BN + LIF(1.0) -> out

#define NC 512
#define NL 1024

__device__ float g_Y[24][NC][NL];                       // 3 branches x 8 batches
__device__ float g_bmean[3][NC];
__device__ float g_binv[3][NC];
__device__ unsigned long long g_KVn[2][4][8][8][64][16]; // [kv][t][b][h][d][n/64]
__device__ unsigned long long g_Qd[4][8][8][NL];         // [t][b][h][n] bits over d
__device__ float g_ktv[4][8][8][64][64];
__device__ float g_X[32][NC][NL];                        // attn-lif spikes (z = t*8+b)
__device__ float g_Z[32][NC][NL];
__device__ float g_fmean[NC];
__device__ float g_finv[NC];

// 4-step LIF with constant input x; returns spike bits (bit t = spike at step t).
// Uses explicitly rounded ops (no FMA contraction) to match the reference op sequence.
__device__ __forceinline__ unsigned lif4_const(float x, float vth) {
    float v = 0.f;
    unsigned bits = 0;
#pragma unroll
    for (int t = 0; t < 4; t++) {
        v = __fadd_rn(v, __fmul_rn(__fsub_rn(x, v), 0.5f));
        if (v >= vth) { bits |= 1u << t; v = 0.f; }
    }
    return bits;
}

// ---------------- fp32 SGEMM: C[M=512,N=1024] = A[512x512] * B[512x1024] + bias ----
__device__ __forceinline__ void sgemm512(const float* __restrict__ A,
                                         const float* __restrict__ B,
                                         float* __restrict__ C,
                                         const float* __restrict__ bias) {
    const int K = 512, N = 1024;
    __shared__ float As[8][128];
    __shared__ float Bs[8][128];
    int tid = threadIdx.x;
    int tx = tid & 15, ty = tid >> 4;
    int rowBase = blockIdx.y * 128, colBase = blockIdx.x * 128;
    int aRow = tid >> 1, aCol = (tid & 1) * 4;
    int bRow = tid >> 5, bCol = (tid & 31) * 4;
    const float* Aptr = A + (rowBase + aRow) * K + aCol;
    const float* Bptr = B + bRow * N + colBase + bCol;
    float acc[8][8];
#pragma unroll
    for (int i = 0; i < 8; i++)
#pragma unroll
        for (int j = 0; j < 8; j++) acc[i][j] = 0.f;

    for (int k0 = 0; k0 < K; k0 += 8) {
        float4 a4 = *(const float4*)Aptr;
        float4 b4 = *(const float4*)Bptr;
        As[aCol + 0][aRow] = a4.x;
        As[aCol + 1][aRow] = a4.y;
        As[aCol + 2][aRow] = a4.z;
        As[aCol + 3][aRow] = a4.w;
        *(float4*)&Bs[bRow][bCol] = b4;
        __syncthreads();
#pragma unroll
        for (int kk = 0; kk < 8; kk++) {
            float ar[8], br[8];
#pragma unroll
            for (int i = 0; i < 8; i++) ar[i] = As[kk][ty * 8 + i];
#pragma unroll
            for (int j = 0; j < 8; j++) br[j] = Bs[kk][tx * 8 + j];
#pragma unroll
            for (int i = 0; i < 8; i++)
#pragma unroll
                for (int j = 0; j < 8; j++) acc[i][j] += ar[i] * br[j];
        }
        __syncthreads();
        Aptr += 8;
        Bptr += 8 * N;
    }
#pragma unroll
    for (int i = 0; i < 8; i++) {
        int m = rowBase + ty * 8 + i;
        float bv = bias[m];
#pragma unroll
        for (int j = 0; j < 8; j += 4) {
            float4 o;
            o.x = acc[i][j + 0] + bv;
            o.y = acc[i][j + 1] + bv;
            o.z = acc[i][j + 2] + bv;
            o.w = acc[i][j + 3] + bv;
            *(float4*)&C[(long)m * N + colBase + tx * 8 + j] = o;
        }
    }
}

__global__ __launch_bounds__(256) void k_gemm1(const float* __restrict__ q,
                                               const float* __restrict__ k,
                                               const float* __restrict__ v,
                                               const float* __restrict__ w,
                                               const float* __restrict__ bias) {
    int z = blockIdx.z;           // 0..23
    int p = z >> 3, b = z & 7;
    const float* src = (p == 0) ? q : (p == 1) ? k : v;
    sgemm512(w + (long)p * NC * NC, src + (long)b * NC * NL, &g_Y[z][0][0], bias + p * NC);
}

__global__ __launch_bounds__(256) void k_gemm3(const float* __restrict__ w,
                                               const float* __restrict__ bias) {
    int z = blockIdx.z;           // 0..31
    sgemm512(w, &g_X[z][0][0], &g_Z[z][0][0], bias);
}

// ---------------- BN stats (fp64 accumulation) ----------------
__device__ __forceinline__ void block_reduce2(double& s1, double& s2) {
    __shared__ double r1[256], r2[256];
    int tid = threadIdx.x;
    r1[tid] = s1; r2[tid] = s2;
    __syncthreads();
    for (int s = 128; s > 0; s >>= 1) {
        if (tid < s) { r1[tid] += r1[tid + s]; r2[tid] += r2[tid + s]; }
        __syncthreads();
    }
    s1 = r1[0]; s2 = r2[0];
}

__global__ __launch_bounds__(256) void k_stats_branch() {
    int p = blockIdx.x >> 9, c = blockIdx.x & 511;
    double s1 = 0.0, s2 = 0.0;
    for (int i = threadIdx.x; i < 8192; i += 256) {
        int b = i >> 10, n = i & 1023;
        float y = g_Y[p * 8 + b][c][n];
        s1 += (double)y;
        s2 += (double)y * (double)y;
    }
    block_reduce2(s1, s2);
    if (threadIdx.x == 0) {
        double m = s1 / 8192.0;
        double var = s2 / 8192.0 - m * m;
        g_bmean[p][c] = (float)m;
        g_binv[p][c] = (float)(1.0 / sqrt(var + 1e-5));
    }
}

__global__ __launch_bounds__(256) void k_stats_final() {
    int c = blockIdx.x;
    double s1 = 0.0, s2 = 0.0;
    for (int i = threadIdx.x; i < 32768; i += 256) {
        int z = i >> 10, n = i & 1023;
        float y = g_Z[z][c][n];
        s1 += (double)y;
        s2 += (double)y * (double)y;
    }
    block_reduce2(s1, s2);
    if (threadIdx.x == 0) {
        double m = s1 / 32768.0;
        double var = s2 / 32768.0 - m * m;
        g_fmean[c] = (float)m;
        g_finv[c] = (float)(1.0 / sqrt(var + 1e-5));
    }
}

// ---------------- spike + pack ----------------
__global__ __launch_bounds__(256) void k_spike_q(const float* __restrict__ gamma,
                                                 const float* __restrict__ beta) {
    int b = blockIdx.x >> 3, h = blockIdx.x & 7;
    __shared__ float sm[64], si[64], sg[64], sb[64];
    if (threadIdx.x < 64) {
        int c = h * 64 + threadIdx.x;
        sm[threadIdx.x] = g_bmean[0][c];
        si[threadIdx.x] = g_binv[0][c];
        sg[threadIdx.x] = gamma[c];
        sb[threadIdx.x] = beta[c];
    }
    __syncthreads();
    for (int rep = 0; rep < 4; rep++) {
        int n = rep * 256 + threadIdx.x;
        unsigned long long bits[4] = {0ull, 0ull, 0ull, 0ull};
        for (int dd = 0; dd < 64; dd++) {
            float y = g_Y[b][h * 64 + dd][n];
            float x = y - sm[dd];
            x = sg[dd] * x;
            x = x * si[dd];
            x = x + sb[dd];
            unsigned s = lif4_const(x, 1.0f);
            bits[0] |= (unsigned long long)(s & 1u) << dd;
            bits[1] |= (unsigned long long)((s >> 1) & 1u) << dd;
            bits[2] |= (unsigned long long)((s >> 2) & 1u) << dd;
            bits[3] |= (unsigned long long)((s >> 3) & 1u) << dd;
        }
#pragma unroll
        for (int t = 0; t < 4; t++) g_Qd[t][b][h][n] = bits[t];
    }
}

__global__ __launch_bounds__(256) void k_spike_kv(const float* __restrict__ kg,
                                                  const float* __restrict__ kb,
                                                  const float* __restrict__ vg,
                                                  const float* __restrict__ vb) {
    int z = blockIdx.x;                 // 0..127
    int p = z >> 6;                     // 0 -> k, 1 -> v
    int bh = z & 63;
    int b = bh >> 3, h = bh & 7;
    const float* gamma = p ? vg : kg;
    const float* beta = p ? vb : kb;
    int pb = p + 1;                     // branch index (1=k, 2=v)
    for (int task = threadIdx.x; task < 1024; task += 256) {
        int dd = task >> 4, nw = task & 15;
        int c = h * 64 + dd;
        float m = g_bmean[pb][c], iv = g_binv[pb][c], gg = gamma[c], bb = beta[c];
        const float* yrow = &g_Y[pb * 8 + b][c][nw * 64];
        unsigned long long bits[4] = {0ull, 0ull, 0ull, 0ull};
        for (int i = 0; i < 64; i++) {
            float x = yrow[i] - m;
            x = gg * x;
            x = x * iv;
            x = x + bb;
            unsigned s = lif4_const(x, 1.0f);
            bits[0] |= (unsigned long long)(s & 1u) << i;
            bits[1] |= (unsigned long long)((s >> 1) & 1u) << i;
            bits[2] |= (unsigned long long)((s >> 2) & 1u) << i;
            bits[3] |= (unsigned long long)((s >> 3) & 1u) << i;
        }
#pragma unroll
        for (int t = 0; t < 4; t++) g_KVn[p][t][b][h][dd][nw] = bits[t];
    }
}

// ---------------- ktv via popcount ----------------
__global__ __launch_bounds__(256) void k_ktv() {
    int z = blockIdx.x;                 // 0..255
    int t = z >> 6;
    int bh = z & 63;
    int b = bh >> 3, h = bh & 7;
    __shared__ unsigned long long Kb[64][16];
    __shared__ unsigned long long Vb[64][16];
    const unsigned long long* ks = &g_KVn[0][t][b][h][0][0];
    const unsigned long long* vs = &g_KVn[1][t][b][h][0][0];
    for (int i = threadIdx.x; i < 1024; i += 256) {
        ((unsigned long long*)Kb)[i] = ks[i];
        ((unsigned long long*)Vb)[i] = vs[i];
    }
    __syncthreads();
    int d = threadIdx.x >> 2;
    int e0 = (threadIdx.x & 3) * 16;
    for (int j = 0; j < 16; j++) {
        int e = e0 + j;
        int s = 0;
#pragma unroll
        for (int w = 0; w < 16; w++) s += __popcll(Kb[d][w] & Vb[e][w]);
        g_ktv[t][b][h][d][e] = (float)s;
    }
}

// ---------------- att (q row-select sum) + attn-LIF(0.5) ----------------
__global__ __launch_bounds__(128) void k_att() {
    int nt = blockIdx.x, h = blockIdx.y, b = blockIdx.z;
    int n = nt * 128 + threadIdx.x;
    __shared__ float sk[2][64][65];
    unsigned long long qb[4];
#pragma unroll
    for (int t = 0; t < 4; t++) qb[t] = g_Qd[t][b][h][n];
    float v[64];
#pragma unroll
    for (int e = 0; e < 64; e++) v[e] = 0.f;

    for (int t = 0; t < 4; t++) {
        if ((t & 1) == 0) {
            __syncthreads();
            for (int i = threadIdx.x; i < 2 * 4096; i += 128) {
                int tt = i >> 12;
                int r = i & 4095;
                sk[tt][r >> 6][r & 63] = g_ktv[t + tt][b][h][r >> 6][r & 63];
            }
            __syncthreads();
        }
        float a[64];
#pragma unroll
        for (int e = 0; e < 64; e++) a[e] = 0.f;
        unsigned long long m = qb[t];
        while (m) {
            int d = __ffsll((long long)m) - 1;
            m &= m - 1;
            const float* row = &sk[t & 1][d][0];
#pragma unroll
            for (int e = 0; e < 64; e++) a[e] += row[e];
        }
        int zo = t * 8 + b;
#pragma unroll
        for (int e = 0; e < 64; e++) {
            float x = a[e] * 0.125f;                 // exact (dyadic integers)
            v[e] = v[e] + (x - v[e]) * 0.5f;         // exact
            float sp = (v[e] >= 0.5f) ? 1.f : 0.f;
            g_X[zo][h * 64 + e][n] = sp;
            v[e] *= (1.f - sp);
        }
    }
}

// ---------------- final BN + LIF(1.0) ----------------
__global__ __launch_bounds__(256) void k_final(const float* __restrict__ gamma,
                                               const float* __restrict__ beta,
                                               float* __restrict__ out) {
    long idx = (long)blockIdx.x * 256 + threadIdx.x;   // 4.19M
    int n = (int)(idx & 1023);
    int c = (int)((idx >> 10) & 511);
    int b = (int)(idx >> 19);
    float m = g_fmean[c], iv = g_finv[c], gg = gamma[c], bb = beta[c];
    float v = 0.f;
#pragma unroll
    for (int t = 0; t < 4; t++) {
        float x = g_Z[t * 8 + b][c][n];
        x = x - m;
        x = gg * x;
        x = x * iv;
        x = x + bb;
        v = __fadd_rn(v, __fmul_rn(__fsub_rn(x, v), 0.5f));
        float s = (v >= 1.0f) ? 1.f : 0.f;
        out[(((long)(t * 8 + b) * NC + c) << 10) + n] = s;
        v *= (1.f - s);
    }
}

extern "C" void kernel_launch(void* const* d_in, const int* in_sizes, int n_in,
                              void* d_out, int out_size) {
    const float* q        = (const float*)d_in[0];
    const float* k        = (const float*)d_in[1];
    const float* v        = (const float*)d_in[2];
    const float* in_w     = (const float*)d_in[3];
    const float* in_b     = (const float*)d_in[4];
    const float* q_gamma  = (const float*)d_in[5];
    const float* q_beta   = (const float*)d_in[6];
    const float* k_gamma  = (const float*)d_in[7];
    const float* k_beta   = (const float*)d_in[8];
    const float* v_gamma  = (const float*)d_in[9];
    const float* v_beta   = (const float*)d_in[10];
    const float* proj_w   = (const float*)d_in[11];
    const float* proj_b   = (const float*)d_in[12];
    const float* p_gamma  = (const float*)d_in[13];
    const float* p_beta   = (const float*)d_in[14];
    float* out = (float*)d_out;

    // K1: branch linear (T-invariant): 24 batched 512x1024x512 fp32 GEMMs
    k_gemm1<<<dim3(NL / 128, NC / 128, 24), 256>>>(q, k, v, in_w, in_b);
    // K2: branch BN stats
    k_stats_branch<<<1536, 256>>>();
    // K3: spikes + bit packing
    k_spike_q<<<64, 256>>>(q_gamma, q_beta);
    k_spike_kv<<<128, 256>>>(k_gamma, k_beta, v_gamma, v_beta);
    // K4: ktv popcounts
    k_ktv<<<256, 256>>>();
    // K5: attention + attn-LIF
    k_att<<<dim3(8, 8, 8), 128>>>();
    // K6: proj linear: 32 batched 512x1024x512 fp32 GEMMs
    k_gemm3<<<dim3(NL / 128, NC / 128, 32), 256>>>(proj_w, proj_b);
    // K7: final BN stats
    k_stats_final<<<512, 256>>>();
    // K8: BN + LIF -> output
    k_final<<<16384, 256>>>(p_gamma, p_beta, out);
}